// round 1
// baseline (speedup 1.0000x reference)
#include <cuda_runtime.h>

#define K_CODES 8192
#define D_DIM   256
#define N_ROWS  32768
#define GAMMA_F 0.99f
#define EPS_F   1e-5f

// Output layout (float32, flattened tuple in reference order)
#define OFF_ZQ     0            /* 32*1024*256 = 8388608 */
#define OFF_COMMIT 8388608      /* 1 */
#define OFF_IDX    8388609      /* 32768 */
#define OFF_EMB    8421377      /* 8192*256 = 2097152 */
#define OFF_MT     10518529     /* 2097152 */
#define OFF_NT     12615681     /* 8192 */

// ---- scratch (device globals; no allocations allowed) ----
__device__ int   g_idx[N_ROWS];
__device__ float g_hn[K_CODES];
__device__ float g_nt[K_CODES];
__device__ float g_st[K_CODES * D_DIM];
__device__ float g_sse;
__device__ float g_nsum;

// packed f32x2 fused multiply-add: two fp32 FMAs per issue slot (sm_100+)
__device__ __forceinline__ void ffma2(unsigned long long &d,
                                      unsigned long long a,
                                      unsigned long long b) {
    asm("fma.rn.f32x2 %0, %1, %2, %0;" : "+l"(d) : "l"(a), "l"(b));
}

__device__ __forceinline__ void unpack2(unsigned long long v, float &lo, float &hi) {
    asm("mov.b64 {%0, %1}, %2;" : "=f"(lo), "=f"(hi) : "l"(v));
}

// ---------------------------------------------------------------------------
// 0) zero scratch accumulators (graph replays require re-zeroing every call)
// ---------------------------------------------------------------------------
__global__ void zero_scratch() {
    int i = blockIdx.x * blockDim.x + threadIdx.x;
    int stride = gridDim.x * blockDim.x;
    for (int q = i; q < K_CODES * D_DIM; q += stride) g_st[q] = 0.0f;
    if (i < K_CODES) g_nt[i] = 0.0f;
    if (i == 0) { g_sse = 0.0f; g_nsum = 0.0f; }
}

// ---------------------------------------------------------------------------
// 1) half squared norms of codebook rows: hn[k] = 0.5 * ||W_k||^2
// ---------------------------------------------------------------------------
__global__ void compute_hn(const float* __restrict__ W) {
    int row  = blockIdx.x * 8 + (threadIdx.x >> 5);
    int lane = threadIdx.x & 31;
    const float4* wr = (const float4*)W + (size_t)row * 64;
    float4 a = wr[lane];
    float4 b = wr[lane + 32];
    float s = a.x*a.x + a.y*a.y + a.z*a.z + a.w*a.w
            + b.x*b.x + b.y*b.y + b.z*b.z + b.w*b.w;
    #pragma unroll
    for (int off = 16; off > 0; off >>= 1)
        s += __shfl_down_sync(0xffffffffu, s, off);
    if (lane == 0) g_hn[row] = 0.5f * s;
}

// ---------------------------------------------------------------------------
// 2) fused GEMM + argmax:  idx[n] = argmax_k ( z_n . w_k - 0.5||w_k||^2 )
//    TM=TN=128, 256 threads, 8x8 micro-tile of f32x2 accumulators.
//    f32x2 lanes = even/odd d-components (no packing, natural float4 layout).
// ---------------------------------------------------------------------------
__global__ __launch_bounds__(256) void gemm_argmin(
    const float* __restrict__ ze, const float* __restrict__ W,
    float* __restrict__ out)
{
    extern __shared__ float4 sm4[];
    float4* zs = sm4;            // [128 rows][64 dvec]  (131072 B)
    float4* ws = sm4 + 128 * 64; // [8 dvl][128 cols]    (16384 B)

    const int tid = threadIdx.x;
    const int tx = tid & 15, ty = tid >> 4;
    const int row0 = blockIdx.x * 128;

    // load z tile once (coalesced, layout-preserving)
    const float4* zg = (const float4*)ze + (size_t)row0 * 64;
    for (int q = tid; q < 128 * 64; q += 256) zs[q] = zg[q];

    float best[8];
    int   bidx[8];
    #pragma unroll
    for (int i = 0; i < 8; i++) { best[i] = -3.0e38f; bidx[i] = 0; }

    __syncthreads();

    for (int kt = 0; kt < K_CODES / 128; kt++) {
        const int col0 = kt * 128;
        unsigned long long acc[8][8];
        #pragma unroll
        for (int i = 0; i < 8; i++)
            #pragma unroll
            for (int j = 0; j < 8; j++) acc[i][j] = 0ull;

        const float4* wg = (const float4*)W + (size_t)col0 * 64;

        for (int c = 0; c < 64; c += 8) {   // 8 dvec (=32 d) chunks
            __syncthreads();
            #pragma unroll
            for (int r = 0; r < 4; r++) {   // coalesced LDG, transposed STS
                int q = tid + r * 256;
                int dvl = q & 7, col = q >> 3;
                ws[dvl * 128 + col] = wg[col * 64 + c + dvl];
            }
            __syncthreads();
            #pragma unroll
            for (int dvl = 0; dvl < 8; dvl++) {
                ulonglong2 zv[8];
                #pragma unroll
                for (int i = 0; i < 8; i++)
                    zv[i] = *reinterpret_cast<const ulonglong2*>(
                        &zs[(ty + 16 * i) * 64 + c + dvl]);
                #pragma unroll
                for (int j = 0; j < 8; j++) {
                    ulonglong2 wv = *reinterpret_cast<const ulonglong2*>(
                        &ws[dvl * 128 + tx + 16 * j]);
                    #pragma unroll
                    for (int i = 0; i < 8; i++) {
                        ffma2(acc[i][j], zv[i].x, wv.x);
                        ffma2(acc[i][j], zv[i].y, wv.y);
                    }
                }
            }
        }
        // epilogue: fold f32x2 halves, subtract half-norm, track argmax
        #pragma unroll
        for (int j = 0; j < 8; j++) {
            int k = col0 + tx + 16 * j;
            float hn = __ldg(&g_hn[k]);
            #pragma unroll
            for (int i = 0; i < 8; i++) {
                float lo, hi;
                unpack2(acc[i][j], lo, hi);
                float s = lo + hi - hn;
                if (s > best[i]) { best[i] = s; bidx[i] = k; } // strict >: lowest k wins ties
            }
        }
    }

    // reduce across the 16 tx-threads sharing each row (16-lane shuffle)
    #pragma unroll
    for (int i = 0; i < 8; i++) {
        float v = best[i];
        int   id = bidx[i];
        #pragma unroll
        for (int off = 8; off > 0; off >>= 1) {
            float ov = __shfl_down_sync(0xffffffffu, v, off, 16);
            int   oi = __shfl_down_sync(0xffffffffu, id, off, 16);
            if (ov > v || (ov == v && oi < id)) { v = ov; id = oi; }
        }
        if (tx == 0) {
            int row = row0 + ty + 16 * i;
            g_idx[row] = id;
            out[OFF_IDX + row] = (float)id;
        }
    }
}

// ---------------------------------------------------------------------------
// 3) gather zq, commit-loss partials, scatter EMA sums/counts
// ---------------------------------------------------------------------------
__global__ void gather_scatter(const float* __restrict__ ze,
                               const float* __restrict__ W,
                               float* __restrict__ out)
{
    __shared__ float wsum[2];
    int row = blockIdx.x;
    int t   = threadIdx.x;            // 64 threads, float4 per thread
    int k   = g_idx[row];

    float4 z = ((const float4*)ze)[(size_t)row * 64 + t];
    float4 w = ((const float4*)W)[(size_t)k * 64 + t];

    ((float4*)(out + OFF_ZQ))[(size_t)row * 64 + t] = w;   // zq_st == zq (value)

    float dx = w.x - z.x, dy = w.y - z.y, dz = w.z - z.z, dw = w.w - z.w;
    float ss = dx*dx + dy*dy + dz*dz + dw*dw;

    int base = k * D_DIM + 4 * t;
    atomicAdd(&g_st[base + 0], z.x);
    atomicAdd(&g_st[base + 1], z.y);
    atomicAdd(&g_st[base + 2], z.z);
    atomicAdd(&g_st[base + 3], z.w);

    #pragma unroll
    for (int off = 16; off > 0; off >>= 1)
        ss += __shfl_down_sync(0xffffffffu, ss, off);
    if ((t & 31) == 0) wsum[t >> 5] = ss;
    __syncthreads();
    if (t == 0) {
        atomicAdd(&g_sse, wsum[0] + wsum[1]);
        atomicAdd(&g_nt[k], 1.0f);
    }
}

// ---------------------------------------------------------------------------
// 4) Nt_new + total count n + commit scalar
// ---------------------------------------------------------------------------
__global__ void finalizeN(const float* __restrict__ Nt, float* __restrict__ out) {
    int k = blockIdx.x * 256 + threadIdx.x;
    float v = GAMMA_F * Nt[k] + (1.0f - GAMMA_F) * g_nt[k];
    out[OFF_NT + k] = v;

    float s = v;
    #pragma unroll
    for (int off = 16; off > 0; off >>= 1)
        s += __shfl_down_sync(0xffffffffu, s, off);
    __shared__ float bs[8];
    if ((threadIdx.x & 31) == 0) bs[threadIdx.x >> 5] = s;
    __syncthreads();
    if (threadIdx.x == 0) {
        float b = 0.0f;
        #pragma unroll
        for (int w = 0; w < 8; w++) b += bs[w];
        atomicAdd(&g_nsum, b);
    }
    if (blockIdx.x == 0 && threadIdx.x == 0)
        out[OFF_COMMIT] = g_sse * (1.0f / (float)(N_ROWS * D_DIM));
}

// ---------------------------------------------------------------------------
// 5) mt_new and embedW_new = mt_new / Nn
// ---------------------------------------------------------------------------
__global__ void finalizeW(const float* __restrict__ mt,
                          const float* __restrict__ Nt,
                          float* __restrict__ out)
{
    int k = blockIdx.x;        // 8192 blocks
    int d = threadIdx.x;       // 256 threads
    float n   = g_nsum;
    float Ntn = GAMMA_F * Nt[k] + (1.0f - GAMMA_F) * g_nt[k];
    float inv = (n + (float)K_CODES * EPS_F) / ((Ntn + EPS_F) * n);
    int q = k * D_DIM + d;
    float m = GAMMA_F * mt[q] + (1.0f - GAMMA_F) * g_st[q];
    out[OFF_MT  + q] = m;
    out[OFF_EMB + q] = m * inv;
}

// ---------------------------------------------------------------------------
extern "C" void kernel_launch(void* const* d_in, const int* in_sizes, int n_in,
                              void* d_out, int out_size)
{
    const float* ze = (const float*)d_in[0];
    const float* W  = (const float*)d_in[1];
    const float* mt = (const float*)d_in[2];
    const float* Nt = (const float*)d_in[3];
    float* out = (float*)d_out;

    const int gemm_smem = 128 * 64 * 16 + 8 * 128 * 16;   // 147456 B
    cudaFuncSetAttribute(gemm_argmin,
                         cudaFuncAttributeMaxDynamicSharedMemorySize, gemm_smem);

    zero_scratch <<<2048, 256>>> ();
    compute_hn   <<<K_CODES / 8, 256>>> (W);
    gemm_argmin  <<<N_ROWS / 128, 256, gemm_smem>>> (ze, W, out);
    gather_scatter<<<N_ROWS, 64>>> (ze, W, out);
    finalizeN    <<<K_CODES / 256, 256>>> (Nt, out);
    finalizeW    <<<K_CODES, 256>>> (mt, Nt, out);
}

// round 6
// speedup vs baseline: 1.0021x; 1.0021x over previous
#include <cuda_runtime.h>

#define K_CODES 8192
#define D_DIM   256
#define N_ROWS  32768
#define GAMMA_F 0.99f
#define EPS_F   1e-5f

// Output layout (float32, flattened tuple in reference order)
#define OFF_ZQ     0            /* 32*1024*256 = 8388608 */
#define OFF_COMMIT 8388608      /* 1 */
#define OFF_IDX    8388609      /* 32768 */
#define OFF_EMB    8421377      /* 8192*256 = 2097152 */
#define OFF_MT     10518529     /* 2097152 */
#define OFF_NT     12615681     /* 8192 */

// ---- scratch (device globals; no allocations allowed) ----
__device__ int   g_idx[N_ROWS];
__device__ float g_hn[K_CODES];
__device__ float g_nt[K_CODES];
__device__ float g_st[K_CODES * D_DIM];
__device__ float g_sse;
__device__ float g_nsum;

// packed f32x2 fused multiply-add: two fp32 FMAs per issue slot (sm_100+)
__device__ __forceinline__ void ffma2(unsigned long long &d,
                                      unsigned long long a,
                                      unsigned long long b) {
    asm("fma.rn.f32x2 %0, %1, %2, %0;" : "+l"(d) : "l"(a), "l"(b));
}

__device__ __forceinline__ void unpack2(unsigned long long v, float &lo, float &hi) {
    asm("mov.b64 {%0, %1}, %2;" : "=f"(lo), "=f"(hi) : "l"(v));
}

// ---------------------------------------------------------------------------
// 0) zero scratch accumulators (graph replays require re-zeroing every call)
// ---------------------------------------------------------------------------
__global__ void zero_scratch() {
    int i = blockIdx.x * blockDim.x + threadIdx.x;
    int stride = gridDim.x * blockDim.x;
    for (int q = i; q < K_CODES * D_DIM; q += stride) g_st[q] = 0.0f;
    if (i < K_CODES) g_nt[i] = 0.0f;
    if (i == 0) { g_sse = 0.0f; g_nsum = 0.0f; }
}

// ---------------------------------------------------------------------------
// 1) half squared norms of codebook rows: hn[k] = 0.5 * ||W_k||^2
// ---------------------------------------------------------------------------
__global__ void compute_hn(const float* __restrict__ W) {
    int row  = blockIdx.x * 8 + (threadIdx.x >> 5);
    int lane = threadIdx.x & 31;
    const float4* wr = (const float4*)W + (size_t)row * 64;
    float4 a = wr[lane];
    float4 b = wr[lane + 32];
    float s = a.x*a.x + a.y*a.y + a.z*a.z + a.w*a.w
            + b.x*b.x + b.y*b.y + b.z*b.z + b.w*b.w;
    #pragma unroll
    for (int off = 16; off > 0; off >>= 1)
        s += __shfl_down_sync(0xffffffffu, s, off);
    if (lane == 0) g_hn[row] = 0.5f * s;
}

// ---------------------------------------------------------------------------
// 2) fused GEMM + argmax:  idx[n] = argmax_k ( z_n . w_k - 0.5||w_k||^2 )
//    TM=TN=128, 256 threads, 8x8 micro-tile of f32x2 accumulators.
//    f32x2 lanes = even/odd d-components (no packing, natural float4 layout).
// ---------------------------------------------------------------------------
__global__ __launch_bounds__(256) void gemm_argmin(
    const float* __restrict__ ze, const float* __restrict__ W,
    float* __restrict__ out)
{
    extern __shared__ float4 sm4[];
    float4* zs = sm4;            // [128 rows][64 dvec]  (131072 B)
    float4* ws = sm4 + 128 * 64; // [8 dvl][128 cols]    (16384 B)

    const int tid = threadIdx.x;
    const int tx = tid & 15, ty = tid >> 4;
    const int row0 = blockIdx.x * 128;

    // load z tile once (coalesced, layout-preserving)
    const float4* zg = (const float4*)ze + (size_t)row0 * 64;
    for (int q = tid; q < 128 * 64; q += 256) zs[q] = zg[q];

    float best[8];
    int   bidx[8];
    #pragma unroll
    for (int i = 0; i < 8; i++) { best[i] = -3.0e38f; bidx[i] = 0; }

    __syncthreads();

    for (int kt = 0; kt < K_CODES / 128; kt++) {
        const int col0 = kt * 128;
        unsigned long long acc[8][8];
        #pragma unroll
        for (int i = 0; i < 8; i++)
            #pragma unroll
            for (int j = 0; j < 8; j++) acc[i][j] = 0ull;

        const float4* wg = (const float4*)W + (size_t)col0 * 64;

        for (int c = 0; c < 64; c += 8) {   // 8 dvec (=32 d) chunks
            __syncthreads();
            #pragma unroll
            for (int r = 0; r < 4; r++) {   // coalesced LDG, transposed STS
                int q = tid + r * 256;
                int dvl = q & 7, col = q >> 3;
                ws[dvl * 128 + col] = wg[col * 64 + c + dvl];
            }
            __syncthreads();
            #pragma unroll
            for (int dvl = 0; dvl < 8; dvl++) {
                ulonglong2 zv[8];
                #pragma unroll
                for (int i = 0; i < 8; i++)
                    zv[i] = *reinterpret_cast<const ulonglong2*>(
                        &zs[(ty + 16 * i) * 64 + c + dvl]);
                #pragma unroll
                for (int j = 0; j < 8; j++) {
                    ulonglong2 wv = *reinterpret_cast<const ulonglong2*>(
                        &ws[dvl * 128 + tx + 16 * j]);
                    #pragma unroll
                    for (int i = 0; i < 8; i++) {
                        ffma2(acc[i][j], zv[i].x, wv.x);
                        ffma2(acc[i][j], zv[i].y, wv.y);
                    }
                }
            }
        }
        // epilogue: fold f32x2 halves, subtract half-norm, track argmax
        #pragma unroll
        for (int j = 0; j < 8; j++) {
            int k = col0 + tx + 16 * j;
            float hn = __ldg(&g_hn[k]);
            #pragma unroll
            for (int i = 0; i < 8; i++) {
                float lo, hi;
                unpack2(acc[i][j], lo, hi);
                float s = lo + hi - hn;
                if (s > best[i]) { best[i] = s; bidx[i] = k; } // strict >: lowest k wins ties
            }
        }
    }

    // reduce across the 16 tx-threads sharing each row (16-lane shuffle)
    #pragma unroll
    for (int i = 0; i < 8; i++) {
        float v = best[i];
        int   id = bidx[i];
        #pragma unroll
        for (int off = 8; off > 0; off >>= 1) {
            float ov = __shfl_down_sync(0xffffffffu, v, off, 16);
            int   oi = __shfl_down_sync(0xffffffffu, id, off, 16);
            if (ov > v || (ov == v && oi < id)) { v = ov; id = oi; }
        }
        if (tx == 0) {
            int row = row0 + ty + 16 * i;
            g_idx[row] = id;
            out[OFF_IDX + row] = (float)id;
        }
    }
}

// ---------------------------------------------------------------------------
// 3) gather zq, commit-loss partials, scatter EMA sums/counts
// ---------------------------------------------------------------------------
__global__ void gather_scatter(const float* __restrict__ ze,
                               const float* __restrict__ W,
                               float* __restrict__ out)
{
    __shared__ float wsum[2];
    int row = blockIdx.x;
    int t   = threadIdx.x;            // 64 threads, float4 per thread
    int k   = g_idx[row];

    float4 z = ((const float4*)ze)[(size_t)row * 64 + t];
    float4 w = ((const float4*)W)[(size_t)k * 64 + t];

    ((float4*)(out + OFF_ZQ))[(size_t)row * 64 + t] = w;   // zq_st == zq (value)

    float dx = w.x - z.x, dy = w.y - z.y, dz = w.z - z.z, dw = w.w - z.w;
    float ss = dx*dx + dy*dy + dz*dz + dw*dw;

    int base = k * D_DIM + 4 * t;
    atomicAdd(&g_st[base + 0], z.x);
    atomicAdd(&g_st[base + 1], z.y);
    atomicAdd(&g_st[base + 2], z.z);
    atomicAdd(&g_st[base + 3], z.w);

    #pragma unroll
    for (int off = 16; off > 0; off >>= 1)
        ss += __shfl_down_sync(0xffffffffu, ss, off);
    if ((t & 31) == 0) wsum[t >> 5] = ss;
    __syncthreads();
    if (t == 0) {
        atomicAdd(&g_sse, wsum[0] + wsum[1]);
        atomicAdd(&g_nt[k], 1.0f);
    }
}

// ---------------------------------------------------------------------------
// 4) Nt_new + total count n + commit scalar
// ---------------------------------------------------------------------------
__global__ void finalizeN(const float* __restrict__ Nt, float* __restrict__ out) {
    int k = blockIdx.x * 256 + threadIdx.x;
    float v = GAMMA_F * Nt[k] + (1.0f - GAMMA_F) * g_nt[k];
    out[OFF_NT + k] = v;

    float s = v;
    #pragma unroll
    for (int off = 16; off > 0; off >>= 1)
        s += __shfl_down_sync(0xffffffffu, s, off);
    __shared__ float bs[8];
    if ((threadIdx.x & 31) == 0) bs[threadIdx.x >> 5] = s;
    __syncthreads();
    if (threadIdx.x == 0) {
        float b = 0.0f;
        #pragma unroll
        for (int w = 0; w < 8; w++) b += bs[w];
        atomicAdd(&g_nsum, b);
    }
    if (blockIdx.x == 0 && threadIdx.x == 0)
        out[OFF_COMMIT] = g_sse * (1.0f / (float)(N_ROWS * D_DIM));
}

// ---------------------------------------------------------------------------
// 5) mt_new and embedW_new = mt_new / Nn
// ---------------------------------------------------------------------------
__global__ void finalizeW(const float* __restrict__ mt,
                          const float* __restrict__ Nt,
                          float* __restrict__ out)
{
    int k = blockIdx.x;        // 8192 blocks
    int d = threadIdx.x;       // 256 threads
    float n   = g_nsum;
    float Ntn = GAMMA_F * Nt[k] + (1.0f - GAMMA_F) * g_nt[k];
    float inv = (n + (float)K_CODES * EPS_F) / ((Ntn + EPS_F) * n);
    int q = k * D_DIM + d;
    float m = GAMMA_F * mt[q] + (1.0f - GAMMA_F) * g_st[q];
    out[OFF_MT  + q] = m;
    out[OFF_EMB + q] = m * inv;
}

// ---------------------------------------------------------------------------
extern "C" void kernel_launch(void* const* d_in, const int* in_sizes, int n_in,
                              void* d_out, int out_size)
{
    const float* ze = (const float*)d_in[0];
    const float* W  = (const float*)d_in[1];
    const float* mt = (const float*)d_in[2];
    const float* Nt = (const float*)d_in[3];
    float* out = (float*)d_out;

    const int gemm_smem = 128 * 64 * 16 + 8 * 128 * 16;   // 147456 B
    cudaFuncSetAttribute(gemm_argmin,
                         cudaFuncAttributeMaxDynamicSharedMemorySize, gemm_smem);

    zero_scratch <<<2048, 256>>> ();
    compute_hn   <<<K_CODES / 8, 256>>> (W);
    gemm_argmin  <<<N_ROWS / 128, 256, gemm_smem>>> (ze, W, out);
    gather_scatter<<<N_ROWS, 64>>> (ze, W, out);
    finalizeN    <<<K_CODES / 256, 256>>> (Nt, out);
    finalizeW    <<<K_CODES, 256>>> (mt, Nt, out);
}

// round 9
// speedup vs baseline: 1.8671x; 1.8632x over previous
#include <cuda_runtime.h>
#include <cstdint>

#define K_CODES 8192
#define D_DIM   256
#define N_ROWS  32768
#define GAMMA_F 0.99f
#define EPS_F   1e-5f

// Output layout (float32, flattened tuple in reference order)
#define OFF_ZQ     0
#define OFF_COMMIT 8388608
#define OFF_IDX    8388609
#define OFF_EMB    8421377
#define OFF_MT     10518529
#define OFF_NT     12615681

#define KHAT 768                    // 3 tf32 segments * 256
#define ROW_TILES (N_ROWS / 128)    // 256
#define COL_TILES (K_CODES / 128)   // 64
#define NCH 24                      // K-chunks of 32 tf32

// ---- scratch (device globals; no allocations allowed) ----
__device__ float g_Ahat[(size_t)N_ROWS * KHAT];   // 96 MB (tf32-valued fp32)
__device__ float g_Bhat[(size_t)K_CODES * KHAT];  // 24 MB
__device__ unsigned long long g_best[N_ROWS];
__device__ float g_hn[K_CODES];
__device__ float g_nt[K_CODES];
__device__ float g_st[K_CODES * D_DIM];
__device__ float g_sse;
__device__ float g_nsum;

// ============================ PTX helpers (base ISA only) ============================
__device__ __forceinline__ uint32_t smem_u32(const void* p) {
    uint32_t a;
    asm("{ .reg .u64 t; cvta.to.shared.u64 t, %1; cvt.u32.u64 %0, t; }"
        : "=r"(a) : "l"(p));
    return a;
}

#define CP_ASYNC16(s, g) \
    asm volatile("cp.async.cg.shared.global [%0], [%1], 16;" :: "r"(s), "l"(g))
#define CP_COMMIT() asm volatile("cp.async.commit_group;" ::: "memory")
#define CP_WAIT(n)  asm volatile("cp.async.wait_group %0;" :: "n"(n) : "memory")

#define LDSM_X4(r0, r1, r2, r3, addr) \
    asm volatile("ldmatrix.sync.aligned.m8n8.x4.shared.b16 {%0,%1,%2,%3}, [%4];" \
                 : "=r"(r0), "=r"(r1), "=r"(r2), "=r"(r3) : "r"(addr))

#define MMA_TF32(c, a, b0, b1) \
    asm volatile("mma.sync.aligned.m16n8k8.row.col.f32.tf32.tf32.f32 " \
                 "{%0,%1,%2,%3}, {%4,%5,%6,%7}, {%8,%9}, {%0,%1,%2,%3};" \
                 : "+f"((c)[0]), "+f"((c)[1]), "+f"((c)[2]), "+f"((c)[3]) \
                 : "r"((a)[0]), "r"((a)[1]), "r"((a)[2]), "r"((a)[3]), \
                   "r"(b0), "r"(b1))

__device__ __forceinline__ float to_tf32(float x) {
    uint32_t u;
    asm("cvt.rna.tf32.f32 %0, %1;" : "=r"(u) : "f"(x));
    return __uint_as_float(u);
}

// ---------------------------------------------------------------------------
// 0) zero scratch (graph replays re-zero every call)
// ---------------------------------------------------------------------------
__global__ void zero_scratch() {
    int i = blockIdx.x * blockDim.x + threadIdx.x;
    int stride = gridDim.x * blockDim.x;
    for (int q = i; q < K_CODES * D_DIM; q += stride) g_st[q] = 0.0f;
    if (i < K_CODES) g_nt[i] = 0.0f;
    for (int q = i; q < N_ROWS; q += stride) g_best[q] = 0ull;
    if (i == 0) { g_sse = 0.0f; g_nsum = 0.0f; }
}

// ---------------------------------------------------------------------------
// 1) half squared norms: hn[k] = 0.5 * ||W_k||^2
// ---------------------------------------------------------------------------
__global__ void compute_hn(const float* __restrict__ W) {
    int row  = blockIdx.x * 8 + (threadIdx.x >> 5);
    int lane = threadIdx.x & 31;
    const float4* wr = (const float4*)W + (size_t)row * 64;
    float4 a = wr[lane];
    float4 b = wr[lane + 32];
    float s = a.x*a.x + a.y*a.y + a.z*a.z + a.w*a.w
            + b.x*b.x + b.y*b.y + b.z*b.z + b.w*b.w;
    #pragma unroll
    for (int off = 16; off > 0; off >>= 1)
        s += __shfl_down_sync(0xffffffffu, s, off);
    if (lane == 0) g_hn[row] = 0.5f * s;
}

// ---------------------------------------------------------------------------
// 2) tf32x3 split: x = hi + mid (tf32 each), residual ~2^-22 rel.
//    A segs = [hi, hi, mid]   B segs = [hi, mid, hi]
//    sum_seg A.B = hi.hi + hi.mid + mid.hi  (mid.mid ~2^-22 dropped)
// ---------------------------------------------------------------------------
__global__ void split_A(const float* __restrict__ ze) {
    int i = blockIdx.x * 256 + threadIdx.x;         // N_ROWS*D_DIM threads
    int n = i >> 8, d = i & 255;
    float x = ze[i];
    float h = to_tf32(x);
    float m = to_tf32(x - h);
    size_t base = (size_t)n * KHAT + d;
    g_Ahat[base +   0] = h;
    g_Ahat[base + 256] = h;
    g_Ahat[base + 512] = m;
}

__global__ void split_B(const float* __restrict__ W) {
    int i = blockIdx.x * 256 + threadIdx.x;         // K_CODES*D_DIM threads
    int n = i >> 8, d = i & 255;
    float x = W[i];
    float h = to_tf32(x);
    float m = to_tf32(x - h);
    size_t base = (size_t)n * KHAT + d;
    g_Bhat[base +   0] = h;
    g_Bhat[base + 256] = m;
    g_Bhat[base + 512] = h;
}

// ---------------------------------------------------------------------------
// 3) mma.sync tf32 GEMM + argmax.  CTA 128x128, BK=32 tf32 (128B rows, SW128
//    swizzle), 8 warps (2m x 4n, warp tile 64x32), 3-stage cp.async pipeline.
// ---------------------------------------------------------------------------
#define STAGE_SZ 32768              // A 16KB + B 16KB
#define SM_HN    (3 * STAGE_SZ)     // 98304
#define SM_TOTAL (SM_HN + 512)      // 98816

__device__ __forceinline__ void load_chunk(uint32_t sstage,
                                           const float* __restrict__ Agp,
                                           const float* __restrict__ Bgp,
                                           int tid) {
    #pragma unroll
    for (int gi = 0; gi < 4; gi++) {
        int q = tid + gi * 256;          // 0..1023 granules per matrix
        int r = q >> 3, c = q & 7;       // row, 16B-chunk
        uint32_t off = (uint32_t)(r * 128 + c * 16);
        uint32_t sw = off ^ ((off >> 3) & 0x70);
        CP_ASYNC16(sstage + sw,         Agp + (size_t)r * KHAT + c * 4);
        CP_ASYNC16(sstage + 16384 + sw, Bgp + (size_t)r * KHAT + c * 4);
    }
}

__global__ __launch_bounds__(256, 2) void gemm_tc() {
    extern __shared__ char smem[];
    const uint32_t sb = smem_u32(smem);
    const int tid = threadIdx.x, lid = tid & 31, wid = tid >> 5;
    const int wm = wid & 1, wn = wid >> 1;      // 2m x 4n warp grid
    const int colT = blockIdx.x & (COL_TILES - 1);
    const int rowT = blockIdx.x >> 6;
    const int row0 = rowT * 128, col0 = colT * 128;

    float* hn_s = (float*)(smem + SM_HN);
    if (tid < 128) hn_s[tid] = g_hn[col0 + tid];

    const float* Ag = g_Ahat + (size_t)row0 * KHAT;
    const float* Bg = g_Bhat + (size_t)col0 * KHAT;

    load_chunk(sb,            Ag,      Bg,      tid); CP_COMMIT();
    load_chunk(sb + STAGE_SZ, Ag + 32, Bg + 32, tid); CP_COMMIT();

    float c[4][4][4];
    #pragma unroll
    for (int i = 0; i < 4; i++)
        #pragma unroll
        for (int j = 0; j < 4; j++)
            #pragma unroll
            for (int q = 0; q < 4; q++) c[i][j][q] = 0.0f;

    // per-lane ldmatrix address components (tf32 fragment mappings)
    const int rA = wm * 64 + ((lid >> 3) & 1) * 8 + (lid & 7);  // + mt*16
    const int cA = (lid >> 4);                                  // + 2*ks
    const int rB = wn * 32 + (lid >> 4) * 8 + (lid & 7);        // + p*16
    const int cB = (lid >> 3) & 1;                              // + 2*ks

    for (int ch = 0; ch < NCH; ch++) {
        if (ch < NCH - 1) CP_WAIT(1); else CP_WAIT(0);
        __syncthreads();
        if (ch + 2 < NCH) {
            load_chunk(sb + ((ch + 2) % 3) * STAGE_SZ,
                       Ag + (ch + 2) * 32, Bg + (ch + 2) * 32, tid);
            CP_COMMIT();
        }
        const uint32_t sA = sb + (ch % 3) * STAGE_SZ;
        const uint32_t sB = sA + 16384;

        #pragma unroll
        for (int ks = 0; ks < 4; ks++) {
            uint32_t a[4][4], b[2][4];
            #pragma unroll
            for (int mt = 0; mt < 4; mt++) {
                uint32_t off = (uint32_t)((rA + mt * 16) * 128 + (cA + 2 * ks) * 16);
                LDSM_X4(a[mt][0], a[mt][1], a[mt][2], a[mt][3],
                        sA + (off ^ ((off >> 3) & 0x70)));
            }
            #pragma unroll
            for (int p = 0; p < 2; p++) {
                uint32_t off = (uint32_t)((rB + p * 16) * 128 + (cB + 2 * ks) * 16);
                LDSM_X4(b[p][0], b[p][1], b[p][2], b[p][3],
                        sB + (off ^ ((off >> 3) & 0x70)));
            }
            #pragma unroll
            for (int mt = 0; mt < 4; mt++)
                #pragma unroll
                for (int nt = 0; nt < 4; nt++)
                    MMA_TF32(c[mt][nt], a[mt],
                             b[nt >> 1][(nt & 1) * 2 + 0],
                             b[nt >> 1][(nt & 1) * 2 + 1]);
        }
    }

    // ---- epilogue: per-row argmax of (dot - hn), merged across CTAs ----
    __syncthreads();
    unsigned long long* sbest = (unsigned long long*)smem;
    if (tid < 128) sbest[tid] = 0ull;
    __syncthreads();

    const int g = lid >> 2, t = lid & 3;
    #pragma unroll
    for (int mt = 0; mt < 4; mt++) {
        #pragma unroll
        for (int rr = 0; rr < 2; rr++) {
            float best = -3.0e38f;
            int bc = 0;
            #pragma unroll
            for (int nt = 0; nt < 4; nt++) {
                #pragma unroll
                for (int j = 0; j < 2; j++) {
                    int ccol = wn * 32 + nt * 8 + 2 * t + j;
                    float v = c[mt][nt][rr * 2 + j] - hn_s[ccol];
                    if (v > best) { best = v; bc = ccol; }   // strict: lowest col on tie
                }
            }
            #pragma unroll
            for (int off = 1; off <= 2; off <<= 1) {
                float ov = __shfl_xor_sync(0xffffffffu, best, off);
                int   oc = __shfl_xor_sync(0xffffffffu, bc, off);
                if (ov > best || (ov == best && oc < bc)) { best = ov; bc = oc; }
            }
            if (t == 0) {
                unsigned u = __float_as_uint(best);
                unsigned key = (u & 0x80000000u) ? ~u : (u | 0x80000000u);
                unsigned long long pk = ((unsigned long long)key << 32)
                                      | (unsigned)(0x0FFFFFFF - (col0 + bc));
                atomicMax(&sbest[wm * 64 + mt * 16 + rr * 8 + g], pk);
            }
        }
    }
    __syncthreads();
    if (tid < 128) atomicMax(&g_best[row0 + tid], sbest[tid]);
}

// ---------------------------------------------------------------------------
// 4) gather zq, commit-loss partials, scatter EMA sums/counts
// ---------------------------------------------------------------------------
__global__ void gather_scatter(const float* __restrict__ ze,
                               const float* __restrict__ W,
                               float* __restrict__ out)
{
    __shared__ float wsum[2];
    int row = blockIdx.x;
    int t   = threadIdx.x;            // 64 threads, float4 per thread
    unsigned long long pk = g_best[row];
    int k = 0x0FFFFFFF - (int)(unsigned)(pk & 0xFFFFFFFFu);

    float4 z = ((const float4*)ze)[(size_t)row * 64 + t];
    float4 w = ((const float4*)W)[(size_t)k * 64 + t];

    ((float4*)(out + OFF_ZQ))[(size_t)row * 64 + t] = w;

    float dx = w.x - z.x, dy = w.y - z.y, dz = w.z - z.z, dw = w.w - z.w;
    float ss = dx*dx + dy*dy + dz*dz + dw*dw;

    int base = k * D_DIM + 4 * t;
    atomicAdd(&g_st[base + 0], z.x);
    atomicAdd(&g_st[base + 1], z.y);
    atomicAdd(&g_st[base + 2], z.z);
    atomicAdd(&g_st[base + 3], z.w);

    #pragma unroll
    for (int off = 16; off > 0; off >>= 1)
        ss += __shfl_down_sync(0xffffffffu, ss, off);
    if ((t & 31) == 0) wsum[t >> 5] = ss;
    __syncthreads();
    if (t == 0) {
        atomicAdd(&g_sse, wsum[0] + wsum[1]);
        atomicAdd(&g_nt[k], 1.0f);
        out[OFF_IDX + row] = (float)k;
    }
}

// ---------------------------------------------------------------------------
// 5) Nt_new + total count n + commit scalar
// ---------------------------------------------------------------------------
__global__ void finalizeN(const float* __restrict__ Nt, float* __restrict__ out) {
    int k = blockIdx.x * 256 + threadIdx.x;
    float v = GAMMA_F * Nt[k] + (1.0f - GAMMA_F) * g_nt[k];
    out[OFF_NT + k] = v;

    float s = v;
    #pragma unroll
    for (int off = 16; off > 0; off >>= 1)
        s += __shfl_down_sync(0xffffffffu, s, off);
    __shared__ float bs[8];
    if ((threadIdx.x & 31) == 0) bs[threadIdx.x >> 5] = s;
    __syncthreads();
    if (threadIdx.x == 0) {
        float b = 0.0f;
        #pragma unroll
        for (int w = 0; w < 8; w++) b += bs[w];
        atomicAdd(&g_nsum, b);
    }
    if (blockIdx.x == 0 && threadIdx.x == 0)
        out[OFF_COMMIT] = g_sse * (1.0f / (float)(N_ROWS * D_DIM));
}

// ---------------------------------------------------------------------------
// 6) mt_new and embedW_new = mt_new / Nn
// ---------------------------------------------------------------------------
__global__ void finalizeW(const float* __restrict__ mt,
                          const float* __restrict__ Nt,
                          float* __restrict__ out)
{
    int k = blockIdx.x;
    int d = threadIdx.x;
    float n   = g_nsum;
    float Ntn = GAMMA_F * Nt[k] + (1.0f - GAMMA_F) * g_nt[k];
    float inv = (n + (float)K_CODES * EPS_F) / ((Ntn + EPS_F) * n);
    int q = k * D_DIM + d;
    float m = GAMMA_F * mt[q] + (1.0f - GAMMA_F) * g_st[q];
    out[OFF_MT  + q] = m;
    out[OFF_EMB + q] = m * inv;
}

// ---------------------------------------------------------------------------
extern "C" void kernel_launch(void* const* d_in, const int* in_sizes, int n_in,
                              void* d_out, int out_size)
{
    const float* ze = (const float*)d_in[0];
    const float* W  = (const float*)d_in[1];
    const float* mt = (const float*)d_in[2];
    const float* Nt = (const float*)d_in[3];
    float* out = (float*)d_out;

    cudaFuncSetAttribute(gemm_tc,
                         cudaFuncAttributeMaxDynamicSharedMemorySize, SM_TOTAL);

    zero_scratch  <<<2048, 256>>> ();
    compute_hn    <<<K_CODES / 8, 256>>> (W);
    split_A       <<<N_ROWS * D_DIM / 256, 256>>> (ze);
    split_B       <<<K_CODES * D_DIM / 256, 256>>> (W);
    gemm_tc       <<<ROW_TILES * COL_TILES, 256, SM_TOTAL>>> ();
    gather_scatter<<<N_ROWS, 64>>> (ze, W, out);
    finalizeN     <<<K_CODES / 256, 256>>> (Nt, out);
    finalizeW     <<<K_CODES, 256>>> (mt, Nt, out);
}

// round 13
// speedup vs baseline: 3.9824x; 2.1329x over previous
#include <cuda_runtime.h>
#include <cstdint>

#define K_CODES 8192
#define D_DIM   256
#define N_ROWS  32768
#define GAMMA_F 0.99f
#define EPS_F   1e-5f

// Output layout (float32, flattened tuple in reference order)
#define OFF_ZQ     0
#define OFF_COMMIT 8388608
#define OFF_IDX    8388609
#define OFF_EMB    8421377
#define OFF_MT     10518529
#define OFF_NT     12615681

#define ROW_TILES (N_ROWS / 128)    // 256
#define COL_TILES (K_CODES / 128)   // 64
#define NCH 8                       // K-chunks of 32 tf32 (K=256)
#define MARGIN 0.5f                 // ~16 sigma of phase-1 score error

// ---- scratch (device globals; no allocations allowed) ----
__device__ float g_Ah[(size_t)N_ROWS * D_DIM];    // 32 MB tf32-rounded ze
__device__ float g_Bh[(size_t)K_CODES * D_DIM];   // 8 MB tf32-rounded W
__device__ unsigned long long g_tb[(size_t)N_ROWS * COL_TILES];  // 16 MB
__device__ unsigned long long g_best[N_ROWS];
__device__ int  g_list[(size_t)COL_TILES * N_ROWS];              // 8 MB
__device__ unsigned int g_cnt[COL_TILES];
__device__ float g_hn[K_CODES];
__device__ float g_nt[K_CODES];
__device__ float g_st[K_CODES * D_DIM];
__device__ float g_sse;
__device__ float g_nsum;

// ============================ PTX helpers (base ISA only) ============================
__device__ __forceinline__ uint32_t smem_u32(const void* p) {
    uint32_t a;
    asm("{ .reg .u64 t; cvta.to.shared.u64 t, %1; cvt.u32.u64 %0, t; }"
        : "=r"(a) : "l"(p));
    return a;
}

#define CP_ASYNC16(s, g) \
    asm volatile("cp.async.cg.shared.global [%0], [%1], 16;" :: "r"(s), "l"(g))
#define CP_COMMIT() asm volatile("cp.async.commit_group;" ::: "memory")
#define CP_WAIT(n)  asm volatile("cp.async.wait_group %0;" :: "n"(n) : "memory")

#define LDSM_X4(r0, r1, r2, r3, addr) \
    asm volatile("ldmatrix.sync.aligned.m8n8.x4.shared.b16 {%0,%1,%2,%3}, [%4];" \
                 : "=r"(r0), "=r"(r1), "=r"(r2), "=r"(r3) : "r"(addr))

#define MMA_TF32(c, a, b0, b1) \
    asm volatile("mma.sync.aligned.m16n8k8.row.col.f32.tf32.tf32.f32 " \
                 "{%0,%1,%2,%3}, {%4,%5,%6,%7}, {%8,%9}, {%0,%1,%2,%3};" \
                 : "+f"((c)[0]), "+f"((c)[1]), "+f"((c)[2]), "+f"((c)[3]) \
                 : "r"((a)[0]), "r"((a)[1]), "r"((a)[2]), "r"((a)[3]), \
                   "r"(b0), "r"(b1))

__device__ __forceinline__ float to_tf32(float x) {
    uint32_t u;
    asm("cvt.rna.tf32.f32 %0, %1;" : "=r"(u) : "f"(x));
    return __uint_as_float(u);
}

__device__ __forceinline__ unsigned long long pack_key(float s, int col) {
    unsigned u = __float_as_uint(s);
    unsigned key = (u & 0x80000000u) ? ~u : (u | 0x80000000u);
    return ((unsigned long long)key << 32) | (unsigned)(0x0FFFFFFF - col);
}
__device__ __forceinline__ float key_score(unsigned long long pk) {
    unsigned key = (unsigned)(pk >> 32);
    unsigned u = (key & 0x80000000u) ? (key & 0x7FFFFFFFu) : ~key;
    return __uint_as_float(u);
}

// ---------------------------------------------------------------------------
// 1) half squared norms: hn[k] = 0.5 * ||W_k||^2   (exact fp32)
// ---------------------------------------------------------------------------
__global__ void compute_hn(const float* __restrict__ W) {
    int row  = blockIdx.x * 8 + (threadIdx.x >> 5);
    int lane = threadIdx.x & 31;
    const float4* wr = (const float4*)W + (size_t)row * 64;
    float4 a = wr[lane];
    float4 b = wr[lane + 32];
    float s = a.x*a.x + a.y*a.y + a.z*a.z + a.w*a.w
            + b.x*b.x + b.y*b.y + b.z*b.z + b.w*b.w;
    #pragma unroll
    for (int off = 16; off > 0; off >>= 1)
        s += __shfl_down_sync(0xffffffffu, s, off);
    if (lane == 0) g_hn[row] = 0.5f * s;
}

// ---------------------------------------------------------------------------
// 2) tf32 rounding (hi part only — phase-1 GEMM input)
// ---------------------------------------------------------------------------
__global__ void split_A(const float4* __restrict__ z4) {
    int i = blockIdx.x * 256 + threadIdx.x;   // 2,097,152 float4s
    float4 v = z4[i];
    v.x = to_tf32(v.x); v.y = to_tf32(v.y); v.z = to_tf32(v.z); v.w = to_tf32(v.w);
    ((float4*)g_Ah)[i] = v;
}
__global__ void split_B(const float4* __restrict__ w4) {
    int i = blockIdx.x * 256 + threadIdx.x;   // 524,288 float4s
    float4 v = w4[i];
    v.x = to_tf32(v.x); v.y = to_tf32(v.y); v.z = to_tf32(v.z); v.w = to_tf32(v.w);
    ((float4*)g_Bh)[i] = v;
}

// ---------------------------------------------------------------------------
// 3) Phase-1: tf32 hi.hi GEMM (K=256) + per-(row, col-tile) approx best.
//    CTA 128x128, BK=32, 8 warps (2m x 4n), 3-stage cp.async pipeline.
// ---------------------------------------------------------------------------
#define STAGE_SZ 32768              // A 16KB + B 16KB
#define SM_HN    (3 * STAGE_SZ)
#define SM_TOTAL (SM_HN + 512)

__device__ __forceinline__ void load_chunk(uint32_t sstage,
                                           const float* __restrict__ Agp,
                                           const float* __restrict__ Bgp,
                                           int tid) {
    #pragma unroll
    for (int gi = 0; gi < 4; gi++) {
        int q = tid + gi * 256;          // 0..1023 granules per matrix
        int r = q >> 3, c = q & 7;
        uint32_t off = (uint32_t)(r * 128 + c * 16);
        uint32_t sw = off ^ ((off >> 3) & 0x70);
        CP_ASYNC16(sstage + sw,         Agp + (size_t)r * D_DIM + c * 4);
        CP_ASYNC16(sstage + 16384 + sw, Bgp + (size_t)r * D_DIM + c * 4);
    }
}

__global__ __launch_bounds__(256, 2) void gemm_p1() {
    extern __shared__ char smem[];
    const uint32_t sb = smem_u32(smem);
    const int tid = threadIdx.x, lid = tid & 31, wid = tid >> 5;
    const int wm = wid & 1, wn = wid >> 1;
    const int colT = blockIdx.x & (COL_TILES - 1);
    const int rowT = blockIdx.x >> 6;
    const int row0 = rowT * 128, col0 = colT * 128;

    if (blockIdx.x == 0 && tid < COL_TILES) g_cnt[tid] = 0;  // for rowreduce

    float* hn_s = (float*)(smem + SM_HN);
    if (tid < 128) hn_s[tid] = g_hn[col0 + tid];

    const float* Ag = g_Ah + (size_t)row0 * D_DIM;
    const float* Bg = g_Bh + (size_t)col0 * D_DIM;

    load_chunk(sb,            Ag,      Bg,      tid); CP_COMMIT();
    load_chunk(sb + STAGE_SZ, Ag + 32, Bg + 32, tid); CP_COMMIT();

    float c[4][4][4];
    #pragma unroll
    for (int i = 0; i < 4; i++)
        #pragma unroll
        for (int j = 0; j < 4; j++)
            #pragma unroll
            for (int q = 0; q < 4; q++) c[i][j][q] = 0.0f;

    const int rA = wm * 64 + ((lid >> 3) & 1) * 8 + (lid & 7);
    const int cA = (lid >> 4);
    const int rB = wn * 32 + (lid >> 4) * 8 + (lid & 7);
    const int cB = (lid >> 3) & 1;

    for (int ch = 0; ch < NCH; ch++) {
        if (ch < NCH - 1) CP_WAIT(1); else CP_WAIT(0);
        __syncthreads();
        if (ch + 2 < NCH) {
            load_chunk(sb + ((ch + 2) % 3) * STAGE_SZ,
                       Ag + (ch + 2) * 32, Bg + (ch + 2) * 32, tid);
            CP_COMMIT();
        }
        const uint32_t sA = sb + (ch % 3) * STAGE_SZ;
        const uint32_t sB = sA + 16384;

        #pragma unroll
        for (int ks = 0; ks < 4; ks++) {
            uint32_t a[4][4], b[2][4];
            #pragma unroll
            for (int mt = 0; mt < 4; mt++) {
                uint32_t off = (uint32_t)((rA + mt * 16) * 128 + (cA + 2 * ks) * 16);
                LDSM_X4(a[mt][0], a[mt][1], a[mt][2], a[mt][3],
                        sA + (off ^ ((off >> 3) & 0x70)));
            }
            #pragma unroll
            for (int p = 0; p < 2; p++) {
                uint32_t off = (uint32_t)((rB + p * 16) * 128 + (cB + 2 * ks) * 16);
                LDSM_X4(b[p][0], b[p][1], b[p][2], b[p][3],
                        sB + (off ^ ((off >> 3) & 0x70)));
            }
            #pragma unroll
            for (int mt = 0; mt < 4; mt++)
                #pragma unroll
                for (int nt = 0; nt < 4; nt++)
                    MMA_TF32(c[mt][nt], a[mt],
                             b[nt >> 1][(nt & 1) * 2 + 0],
                             b[nt >> 1][(nt & 1) * 2 + 1]);
        }
    }

    // ---- epilogue: per-row approx best within this 128-col tile ----
    __syncthreads();
    unsigned long long* sbest = (unsigned long long*)smem;
    if (tid < 128) sbest[tid] = 0ull;
    __syncthreads();

    const int g = lid >> 2, t = lid & 3;
    #pragma unroll
    for (int mt = 0; mt < 4; mt++) {
        #pragma unroll
        for (int rr = 0; rr < 2; rr++) {
            float best = -3.0e38f;
            int bc = 0;
            #pragma unroll
            for (int nt = 0; nt < 4; nt++) {
                #pragma unroll
                for (int j = 0; j < 2; j++) {
                    int ccol = wn * 32 + nt * 8 + 2 * t + j;
                    float v = c[mt][nt][rr * 2 + j] - hn_s[ccol];
                    if (v > best) { best = v; bc = ccol; }
                }
            }
            #pragma unroll
            for (int off = 1; off <= 2; off <<= 1) {
                float ov = __shfl_xor_sync(0xffffffffu, best, off);
                int   oc = __shfl_xor_sync(0xffffffffu, bc, off);
                if (ov > best || (ov == best && oc < bc)) { best = ov; bc = oc; }
            }
            if (t == 0)
                atomicMax(&sbest[wm * 64 + mt * 16 + rr * 8 + g],
                          pack_key(best, col0 + bc));
        }
    }
    __syncthreads();
    if (tid < 128)
        g_tb[(size_t)(row0 + tid) * COL_TILES + colT] = sbest[tid];
}

// ---------------------------------------------------------------------------
// 4) per-row reduce over 64 tiles; build candidate tile lists (margin filter)
// ---------------------------------------------------------------------------
__global__ void rowreduce() {
    int row  = blockIdx.x * 8 + (threadIdx.x >> 5);
    int lane = threadIdx.x & 31;
    if (blockIdx.x == 0 && threadIdx.x == 0) g_sse = 0.0f;

    unsigned long long a = g_tb[(size_t)row * COL_TILES + lane];
    unsigned long long b = g_tb[(size_t)row * COL_TILES + lane + 32];
    unsigned long long m = a > b ? a : b;
    #pragma unroll
    for (int off = 16; off > 0; off >>= 1) {
        unsigned long long o = __shfl_xor_sync(0xffffffffu, m, off);
        if (o > m) m = o;
    }
    float thr = key_score(m) - MARGIN;
    if (key_score(a) >= thr) {
        unsigned slot = atomicAdd(&g_cnt[lane], 1u);
        g_list[(size_t)lane * N_ROWS + slot] = row;
    }
    if (key_score(b) >= thr) {
        unsigned slot = atomicAdd(&g_cnt[lane + 32], 1u);
        g_list[(size_t)(lane + 32) * N_ROWS + slot] = row;
    }
    if (lane == 0) g_best[row] = 0ull;
}

// ---------------------------------------------------------------------------
// 5) exact fp32 rescore of candidate (row, tile) pairs; merge via atomicMax
//    grid = 64 tiles x 8 CTAs; block 256 (8 warps); 8-row batches per warp.
// ---------------------------------------------------------------------------
#define WT_STRIDE 257
#define RS_WT_FLOATS (128 * WT_STRIDE)                 // 32896
#define RS_Z_OFF   RS_WT_FLOATS                        // 8 warps * 8 rows * 256
#define RS_HN_OFF  (RS_Z_OFF + 8 * 8 * 256)
#define RS_SMEM    ((RS_HN_OFF + 128) * 4)             // bytes

__global__ __launch_bounds__(256, 1) void rescore(const float* __restrict__ ze,
                                                  const float* __restrict__ W) {
    extern __shared__ float sm[];
    float* Wt   = sm;
    float* zall = sm + RS_Z_OFF;
    float* hn_s = sm + RS_HN_OFF;

    const int tid = threadIdx.x, lane = tid & 31, warp = tid >> 5;
    const int tile = blockIdx.x >> 3, sub = blockIdx.x & 7;
    const int col0 = tile * 128;
    const unsigned cnt = g_cnt[tile];

    // load W tile [128 cols][256 d] fp32 -> stride-257 smem (conflict-free)
    const float4* W4 = (const float4*)W;
    for (int idx = tid; idx < 128 * 64; idx += 256) {
        int col = idx >> 6, d4 = idx & 63;
        float4 v = W4[(size_t)(col0 + col) * 64 + d4];
        float* p = Wt + col * WT_STRIDE + d4 * 4;
        p[0] = v.x; p[1] = v.y; p[2] = v.z; p[3] = v.w;
    }
    if (tid < 128) hn_s[tid] = g_hn[col0 + tid];
    __syncthreads();

    const float4* z4 = (const float4*)ze;
    float* zb = zall + warp * (8 * 256);
    const int warpg = sub * 8 + warp;                 // 0..63
    const unsigned nbatch = (cnt + 7) >> 3;

    for (unsigned b = warpg; b < nbatch; b += 64) {
        int rows[8];
        int nval = (int)cnt - (int)(b * 8);
        if (nval > 8) nval = 8;
        #pragma unroll
        for (int r = 0; r < 8; r++) {
            int li = (int)(b * 8) + r;
            rows[r] = g_list[(size_t)tile * N_ROWS + (r < nval ? li : (int)(b * 8))];
        }
        // stage z rows into smem (each lane: 8 floats per row)
        #pragma unroll
        for (int r = 0; r < 8; r++) {
            float4 z0 = z4[(size_t)rows[r] * 64 + lane * 2];
            float4 z1 = z4[(size_t)rows[r] * 64 + lane * 2 + 1];
            *(float4*)(zb + r * 256 + lane * 8)     = z0;
            *(float4*)(zb + r * 256 + lane * 8 + 4) = z1;
        }
        __syncwarp();

        float acc[8][4];
        #pragma unroll
        for (int r = 0; r < 8; r++)
            #pragma unroll
            for (int q = 0; q < 4; q++) acc[r][q] = 0.0f;

        for (int d4 = 0; d4 < 64; d4++) {
            float w[4][4];
            #pragma unroll
            for (int q = 0; q < 4; q++) {
                const float* wp = Wt + (lane + 32 * q) * WT_STRIDE + d4 * 4;
                w[q][0] = wp[0]; w[q][1] = wp[1]; w[q][2] = wp[2]; w[q][3] = wp[3];
            }
            #pragma unroll
            for (int r = 0; r < 8; r++) {
                float4 z = *(const float4*)(zb + r * 256 + d4 * 4);
                #pragma unroll
                for (int q = 0; q < 4; q++)
                    acc[r][q] += z.x * w[q][0] + z.y * w[q][1]
                               + z.z * w[q][2] + z.w * w[q][3];
            }
        }

        #pragma unroll
        for (int r = 0; r < 8; r++) {
            if (r >= nval) break;        // warp-uniform
            float best = -3.0e38f;
            int bc = 0;
            #pragma unroll
            for (int q = 0; q < 4; q++) {
                int ccol = lane + 32 * q;
                float s = acc[r][q] - hn_s[ccol];
                if (s > best) { best = s; bc = ccol; }
            }
            #pragma unroll
            for (int off = 1; off <= 16; off <<= 1) {
                float ov = __shfl_xor_sync(0xffffffffu, best, off);
                int   oc = __shfl_xor_sync(0xffffffffu, bc, off);
                if (ov > best || (ov == best && oc < bc)) { best = ov; bc = oc; }
            }
            if (lane == 0)
                atomicMax(&g_best[rows[r]], pack_key(best, col0 + bc));
        }
        __syncwarp();
    }
}

// ---------------------------------------------------------------------------
// 6) gather zq, commit-loss partials, scatter EMA sums/counts
// ---------------------------------------------------------------------------
__global__ void gather_scatter(const float* __restrict__ ze,
                               const float* __restrict__ W,
                               float* __restrict__ out)
{
    __shared__ float wsum[2];
    int row = blockIdx.x;
    int t   = threadIdx.x;            // 64 threads, float4 per thread
    if (row == 0 && t == 0) g_nsum = 0.0f;
    unsigned long long pk = g_best[row];
    int k = 0x0FFFFFFF - (int)(unsigned)(pk & 0xFFFFFFFFu);

    float4 z = ((const float4*)ze)[(size_t)row * 64 + t];
    float4 w = ((const float4*)W)[(size_t)k * 64 + t];

    ((float4*)(out + OFF_ZQ))[(size_t)row * 64 + t] = w;

    float dx = w.x - z.x, dy = w.y - z.y, dz = w.z - z.z, dw = w.w - z.w;
    float ss = dx*dx + dy*dy + dz*dz + dw*dw;

    int base = k * D_DIM + 4 * t;
    atomicAdd(&g_st[base + 0], z.x);
    atomicAdd(&g_st[base + 1], z.y);
    atomicAdd(&g_st[base + 2], z.z);
    atomicAdd(&g_st[base + 3], z.w);

    #pragma unroll
    for (int off = 16; off > 0; off >>= 1)
        ss += __shfl_down_sync(0xffffffffu, ss, off);
    if ((t & 31) == 0) wsum[t >> 5] = ss;
    __syncthreads();
    if (t == 0) {
        atomicAdd(&g_sse, wsum[0] + wsum[1]);
        atomicAdd(&g_nt[k], 1.0f);
        out[OFF_IDX + row] = (float)k;
    }
}

// ---------------------------------------------------------------------------
// 7) Nt_new + total count n + commit scalar
// ---------------------------------------------------------------------------
__global__ void finalizeN(const float* __restrict__ Nt, float* __restrict__ out) {
    int k = blockIdx.x * 256 + threadIdx.x;
    float v = GAMMA_F * Nt[k] + (1.0f - GAMMA_F) * g_nt[k];
    out[OFF_NT + k] = v;

    float s = v;
    #pragma unroll
    for (int off = 16; off > 0; off >>= 1)
        s += __shfl_down_sync(0xffffffffu, s, off);
    __shared__ float bs[8];
    if ((threadIdx.x & 31) == 0) bs[threadIdx.x >> 5] = s;
    __syncthreads();
    if (threadIdx.x == 0) {
        float b = 0.0f;
        #pragma unroll
        for (int w = 0; w < 8; w++) b += bs[w];
        atomicAdd(&g_nsum, b);
    }
    if (blockIdx.x == 0 && threadIdx.x == 0)
        out[OFF_COMMIT] = g_sse * (1.0f / (float)(N_ROWS * D_DIM));
}

// ---------------------------------------------------------------------------
// 8) mt_new, embedW_new = mt_new / Nn; read-then-zero the EMA scratch
// ---------------------------------------------------------------------------
__global__ void finalizeW(const float* __restrict__ mt,
                          const float* __restrict__ Nt,
                          float* __restrict__ out)
{
    int k = blockIdx.x;
    int d = threadIdx.x;
    float n   = g_nsum;
    float Ntn = GAMMA_F * Nt[k] + (1.0f - GAMMA_F) * g_nt[k];
    float inv = (n + (float)K_CODES * EPS_F) / ((Ntn + EPS_F) * n);
    int q = k * D_DIM + d;
    float m = GAMMA_F * mt[q] + (1.0f - GAMMA_F) * g_st[q];
    out[OFF_MT  + q] = m;
    out[OFF_EMB + q] = m * inv;
    g_st[q] = 0.0f;                       // re-zero for next graph replay
    __syncthreads();
    if (d == 0) g_nt[k] = 0.0f;
}

// ---------------------------------------------------------------------------
extern "C" void kernel_launch(void* const* d_in, const int* in_sizes, int n_in,
                              void* d_out, int out_size)
{
    const float* ze = (const float*)d_in[0];
    const float* W  = (const float*)d_in[1];
    const float* mt = (const float*)d_in[2];
    const float* Nt = (const float*)d_in[3];
    float* out = (float*)d_out;

    cudaFuncSetAttribute(gemm_p1,
                         cudaFuncAttributeMaxDynamicSharedMemorySize, SM_TOTAL);
    cudaFuncSetAttribute(rescore,
                         cudaFuncAttributeMaxDynamicSharedMemorySize, RS_SMEM);

    compute_hn    <<<K_CODES / 8, 256>>> (W);
    split_A       <<<N_ROWS * 64 / 256, 256>>> ((const float4*)ze);
    split_B       <<<K_CODES * 64 / 256, 256>>> ((const float4*)W);
    gemm_p1       <<<ROW_TILES * COL_TILES, 256, SM_TOTAL>>> ();
    rowreduce     <<<N_ROWS / 8, 256>>> ();
    rescore       <<<COL_TILES * 8, 256, RS_SMEM>>> (ze, W);
    gather_scatter<<<N_ROWS, 64>>> (ze, W, out);
    finalizeN     <<<K_CODES / 256, 256>>> (Nt, out);
    finalizeW     <<<K_CODES, 256>>> (mt, Nt, out);
}

// round 15
// speedup vs baseline: 6.4347x; 1.6158x over previous
#include <cuda_runtime.h>
#include <cuda_bf16.h>
#include <cstdint>

#define K_CODES 8192
#define D_DIM   256
#define N_ROWS  32768
#define GAMMA_F 0.99f
#define EPS_F   1e-5f

// Output layout (float32, flattened tuple in reference order)
#define OFF_ZQ     0
#define OFF_COMMIT 8388608
#define OFF_IDX    8388609
#define OFF_EMB    8421377
#define OFF_MT     10518529
#define OFF_NT     12615681

#define ROW_TILES (N_ROWS / 128)    // 256
#define COL_TILES (K_CODES / 128)   // 64
#define NCH 4                       // K-chunks of 64 bf16 (K=256)
#define MARGIN 0.5f                 // >20 sigma of bf16 phase-1 score error

// ---- scratch (device globals; no allocations allowed) ----
__device__ __nv_bfloat16 g_Ah[(size_t)N_ROWS * D_DIM];   // 16 MB
__device__ __nv_bfloat16 g_Bh[(size_t)K_CODES * D_DIM];  // 4 MB
__device__ unsigned long long g_tb[(size_t)N_ROWS * COL_TILES];  // 16 MB
__device__ unsigned long long g_best[N_ROWS];
__device__ int  g_list[(size_t)COL_TILES * N_ROWS];              // 8 MB
__device__ unsigned int g_cnt[COL_TILES];
__device__ float g_hn[K_CODES];
__device__ float g_nt[K_CODES];
__device__ float g_st[K_CODES * D_DIM];
__device__ float g_sse;
__device__ float g_nsum;

// ============================ PTX helpers (base ISA only) ============================
__device__ __forceinline__ uint32_t smem_u32(const void* p) {
    uint32_t a;
    asm("{ .reg .u64 t; cvta.to.shared.u64 t, %1; cvt.u32.u64 %0, t; }"
        : "=r"(a) : "l"(p));
    return a;
}

#define CP_ASYNC16(s, g) \
    asm volatile("cp.async.cg.shared.global [%0], [%1], 16;" :: "r"(s), "l"(g))
#define CP_COMMIT() asm volatile("cp.async.commit_group;" ::: "memory")
#define CP_WAIT(n)  asm volatile("cp.async.wait_group %0;" :: "n"(n) : "memory")

#define LDSM_X4(r0, r1, r2, r3, addr) \
    asm volatile("ldmatrix.sync.aligned.m8n8.x4.shared.b16 {%0,%1,%2,%3}, [%4];" \
                 : "=r"(r0), "=r"(r1), "=r"(r2), "=r"(r3) : "r"(addr))

#define MMA_BF16(c, a, b0, b1) \
    asm volatile("mma.sync.aligned.m16n8k16.row.col.f32.bf16.bf16.f32 " \
                 "{%0,%1,%2,%3}, {%4,%5,%6,%7}, {%8,%9}, {%0,%1,%2,%3};" \
                 : "+f"((c)[0]), "+f"((c)[1]), "+f"((c)[2]), "+f"((c)[3]) \
                 : "r"((a)[0]), "r"((a)[1]), "r"((a)[2]), "r"((a)[3]), \
                   "r"(b0), "r"(b1))

__device__ __forceinline__ unsigned long long pack_key(float s, int col) {
    unsigned u = __float_as_uint(s);
    unsigned key = (u & 0x80000000u) ? ~u : (u | 0x80000000u);
    return ((unsigned long long)key << 32) | (unsigned)(0x0FFFFFFF - col);
}
__device__ __forceinline__ float key_score(unsigned long long pk) {
    unsigned key = (unsigned)(pk >> 32);
    unsigned u = (key & 0x80000000u) ? (key & 0x7FFFFFFFu) : ~key;
    return __uint_as_float(u);
}

// ---------------------------------------------------------------------------
// 1) half squared norms: hn[k] = 0.5 * ||W_k||^2   (exact fp32)
// ---------------------------------------------------------------------------
__global__ void compute_hn(const float* __restrict__ W) {
    int row  = blockIdx.x * 8 + (threadIdx.x >> 5);
    int lane = threadIdx.x & 31;
    const float4* wr = (const float4*)W + (size_t)row * 64;
    float4 a = wr[lane];
    float4 b = wr[lane + 32];
    float s = a.x*a.x + a.y*a.y + a.z*a.z + a.w*a.w
            + b.x*b.x + b.y*b.y + b.z*b.z + b.w*b.w;
    #pragma unroll
    for (int off = 16; off > 0; off >>= 1)
        s += __shfl_down_sync(0xffffffffu, s, off);
    if (lane == 0) g_hn[row] = 0.5f * s;
}

// ---------------------------------------------------------------------------
// 2) bf16 rounding (phase-1 GEMM input)
// ---------------------------------------------------------------------------
__global__ void split_A(const float4* __restrict__ z4) {
    int i = blockIdx.x * 256 + threadIdx.x;   // N_ROWS*64 float4s
    float4 v = z4[i];
    __nv_bfloat162 lo = __floats2bfloat162_rn(v.x, v.y);
    __nv_bfloat162 hi = __floats2bfloat162_rn(v.z, v.w);
    uint2 pk = { *(uint32_t*)&lo, *(uint32_t*)&hi };
    ((uint2*)g_Ah)[i] = pk;
}
__global__ void split_B(const float4* __restrict__ w4) {
    int i = blockIdx.x * 256 + threadIdx.x;   // K_CODES*64 float4s
    float4 v = w4[i];
    __nv_bfloat162 lo = __floats2bfloat162_rn(v.x, v.y);
    __nv_bfloat162 hi = __floats2bfloat162_rn(v.z, v.w);
    uint2 pk = { *(uint32_t*)&lo, *(uint32_t*)&hi };
    ((uint2*)g_Bh)[i] = pk;
}

// ---------------------------------------------------------------------------
// 3) Phase-1: bf16 GEMM (K=256) + per-(row, col-tile) approx best.
//    CTA 128x128, BK=64 bf16 (128B rows, SW128), 8 warps (2m x 4n),
//    3-stage cp.async pipeline, mma.m16n8k16.bf16.
// ---------------------------------------------------------------------------
#define STAGE_SZ 32768              // A 16KB + B 16KB
#define SM_HN    (3 * STAGE_SZ)
#define SM_TOTAL (SM_HN + 512)

__device__ __forceinline__ void load_chunk(uint32_t sstage,
                                           const __nv_bfloat16* __restrict__ Agp,
                                           const __nv_bfloat16* __restrict__ Bgp,
                                           int tid) {
    #pragma unroll
    for (int gi = 0; gi < 4; gi++) {
        int q = tid + gi * 256;          // 0..1023 granules per matrix
        int r = q >> 3, c = q & 7;       // row, 16B-chunk (8 bf16)
        uint32_t off = (uint32_t)(r * 128 + c * 16);
        uint32_t sw = off ^ ((off >> 3) & 0x70);
        CP_ASYNC16(sstage + sw,         Agp + (size_t)r * D_DIM + c * 8);
        CP_ASYNC16(sstage + 16384 + sw, Bgp + (size_t)r * D_DIM + c * 8);
    }
}

__global__ __launch_bounds__(256, 2) void gemm_p1() {
    extern __shared__ char smem[];
    const uint32_t sb = smem_u32(smem);
    const int tid = threadIdx.x, lid = tid & 31, wid = tid >> 5;
    const int wm = wid & 1, wn = wid >> 1;
    const int colT = blockIdx.x & (COL_TILES - 1);
    const int rowT = blockIdx.x >> 6;
    const int row0 = rowT * 128, col0 = colT * 128;

    if (blockIdx.x == 0 && tid < COL_TILES) g_cnt[tid] = 0;  // for rowreduce

    float* hn_s = (float*)(smem + SM_HN);
    if (tid < 128) hn_s[tid] = g_hn[col0 + tid];

    const __nv_bfloat16* Ag = g_Ah + (size_t)row0 * D_DIM;
    const __nv_bfloat16* Bg = g_Bh + (size_t)col0 * D_DIM;

    load_chunk(sb,            Ag,      Bg,      tid); CP_COMMIT();
    load_chunk(sb + STAGE_SZ, Ag + 64, Bg + 64, tid); CP_COMMIT();

    float c[4][4][4];
    #pragma unroll
    for (int i = 0; i < 4; i++)
        #pragma unroll
        for (int j = 0; j < 4; j++)
            #pragma unroll
            for (int q = 0; q < 4; q++) c[i][j][q] = 0.0f;

    // ldmatrix lane address components (m16n8k16 bf16 fragment mappings)
    const int rA  = (lid & 7) + ((lid >> 3) & 1) * 8;   // + wm*64 + mt*16
    const int cA  = (lid >> 4) & 1;                     // 16B half (k8)
    const int rB  = (lid & 7) + ((lid >> 4) & 1) * 8;   // + wn*32 + p*16
    const int cB  = (lid >> 3) & 1;                     // 16B half (k8)

    for (int ch = 0; ch < NCH; ch++) {
        if (ch < NCH - 1) CP_WAIT(1); else CP_WAIT(0);
        __syncthreads();
        if (ch + 2 < NCH) {
            load_chunk(sb + ((ch + 2) % 3) * STAGE_SZ,
                       Ag + (ch + 2) * 64, Bg + (ch + 2) * 64, tid);
            CP_COMMIT();
        }
        const uint32_t sA = sb + (ch % 3) * STAGE_SZ;
        const uint32_t sB = sA + 16384;

        #pragma unroll
        for (int ks = 0; ks < 4; ks++) {              // 4 x k16 = 64
            uint32_t a[4][4], b[2][4];
            #pragma unroll
            for (int mt = 0; mt < 4; mt++) {
                uint32_t off = (uint32_t)((wm * 64 + mt * 16 + rA) * 128
                                          + ks * 32 + cA * 16);
                LDSM_X4(a[mt][0], a[mt][1], a[mt][2], a[mt][3],
                        sA + (off ^ ((off >> 3) & 0x70)));
            }
            #pragma unroll
            for (int p = 0; p < 2; p++) {
                uint32_t off = (uint32_t)((wn * 32 + p * 16 + rB) * 128
                                          + ks * 32 + cB * 16);
                LDSM_X4(b[p][0], b[p][1], b[p][2], b[p][3],
                        sB + (off ^ ((off >> 3) & 0x70)));
            }
            #pragma unroll
            for (int mt = 0; mt < 4; mt++)
                #pragma unroll
                for (int nt = 0; nt < 4; nt++)
                    MMA_BF16(c[mt][nt], a[mt],
                             b[nt >> 1][(nt & 1) * 2 + 0],
                             b[nt >> 1][(nt & 1) * 2 + 1]);
        }
    }

    // ---- epilogue: per-row approx best within this 128-col tile ----
    __syncthreads();
    unsigned long long* sbest = (unsigned long long*)smem;
    if (tid < 128) sbest[tid] = 0ull;
    __syncthreads();

    const int g = lid >> 2, t = lid & 3;
    #pragma unroll
    for (int mt = 0; mt < 4; mt++) {
        #pragma unroll
        for (int rr = 0; rr < 2; rr++) {
            float best = -3.0e38f;
            int bc = 0;
            #pragma unroll
            for (int nt = 0; nt < 4; nt++) {
                #pragma unroll
                for (int j = 0; j < 2; j++) {
                    int ccol = wn * 32 + nt * 8 + 2 * t + j;
                    float v = c[mt][nt][rr * 2 + j] - hn_s[ccol];
                    if (v > best) { best = v; bc = ccol; }
                }
            }
            #pragma unroll
            for (int off = 1; off <= 2; off <<= 1) {
                float ov = __shfl_xor_sync(0xffffffffu, best, off);
                int   oc = __shfl_xor_sync(0xffffffffu, bc, off);
                if (ov > best || (ov == best && oc < bc)) { best = ov; bc = oc; }
            }
            if (t == 0)
                atomicMax(&sbest[wm * 64 + mt * 16 + rr * 8 + g],
                          pack_key(best, col0 + bc));
        }
    }
    __syncthreads();
    if (tid < 128)
        g_tb[(size_t)(row0 + tid) * COL_TILES + colT] = sbest[tid];
}

// ---------------------------------------------------------------------------
// 4) per-row reduce over 64 tiles; build candidate tile lists (margin filter)
// ---------------------------------------------------------------------------
__global__ void rowreduce() {
    int row  = blockIdx.x * 8 + (threadIdx.x >> 5);
    int lane = threadIdx.x & 31;
    if (blockIdx.x == 0 && threadIdx.x == 0) g_sse = 0.0f;

    unsigned long long a = g_tb[(size_t)row * COL_TILES + lane];
    unsigned long long b = g_tb[(size_t)row * COL_TILES + lane + 32];
    unsigned long long m = a > b ? a : b;
    #pragma unroll
    for (int off = 16; off > 0; off >>= 1) {
        unsigned long long o = __shfl_xor_sync(0xffffffffu, m, off);
        if (o > m) m = o;
    }
    float thr = key_score(m) - MARGIN;
    if (key_score(a) >= thr) {
        unsigned slot = atomicAdd(&g_cnt[lane], 1u);
        g_list[(size_t)lane * N_ROWS + slot] = row;
    }
    if (key_score(b) >= thr) {
        unsigned slot = atomicAdd(&g_cnt[lane + 32], 1u);
        g_list[(size_t)(lane + 32) * N_ROWS + slot] = row;
    }
    if (lane == 0) g_best[row] = 0ull;
}

// ---------------------------------------------------------------------------
// 5) exact fp32 rescore of candidate (row, tile) pairs; merge via atomicMax
//    grid = 64 tiles x 8 CTAs; block 256 (8 warps); 8-row batches per warp.
// ---------------------------------------------------------------------------
#define WT_STRIDE 257
#define RS_WT_FLOATS (128 * WT_STRIDE)                 // 32896
#define RS_Z_OFF   RS_WT_FLOATS
#define RS_HN_OFF  (RS_Z_OFF + 8 * 8 * 256)
#define RS_SMEM    ((RS_HN_OFF + 128) * 4)             // bytes

__global__ __launch_bounds__(256, 1) void rescore(const float* __restrict__ ze,
                                                  const float* __restrict__ W) {
    extern __shared__ float sm[];
    float* Wt   = sm;
    float* zall = sm + RS_Z_OFF;
    float* hn_s = sm + RS_HN_OFF;

    const int tid = threadIdx.x, lane = tid & 31, warp = tid >> 5;
    const int tile = blockIdx.x >> 3, sub = blockIdx.x & 7;
    const int col0 = tile * 128;
    const unsigned cnt = g_cnt[tile];

    // load W tile [128 cols][256 d] fp32 -> stride-257 smem (conflict-free)
    const float4* W4 = (const float4*)W;
    for (int idx = tid; idx < 128 * 64; idx += 256) {
        int col = idx >> 6, d4 = idx & 63;
        float4 v = W4[(size_t)(col0 + col) * 64 + d4];
        float* p = Wt + col * WT_STRIDE + d4 * 4;
        p[0] = v.x; p[1] = v.y; p[2] = v.z; p[3] = v.w;
    }
    if (tid < 128) hn_s[tid] = g_hn[col0 + tid];
    __syncthreads();

    const float4* z4 = (const float4*)ze;
    float* zb = zall + warp * (8 * 256);
    const int warpg = sub * 8 + warp;                 // 0..63
    const unsigned nbatch = (cnt + 7) >> 3;

    for (unsigned b = warpg; b < nbatch; b += 64) {
        int rows[8];
        int nval = (int)cnt - (int)(b * 8);
        if (nval > 8) nval = 8;
        #pragma unroll
        for (int r = 0; r < 8; r++) {
            int li = (int)(b * 8) + r;
            rows[r] = g_list[(size_t)tile * N_ROWS + (r < nval ? li : (int)(b * 8))];
        }
        #pragma unroll
        for (int r = 0; r < 8; r++) {
            float4 z0 = z4[(size_t)rows[r] * 64 + lane * 2];
            float4 z1 = z4[(size_t)rows[r] * 64 + lane * 2 + 1];
            *(float4*)(zb + r * 256 + lane * 8)     = z0;
            *(float4*)(zb + r * 256 + lane * 8 + 4) = z1;
        }
        __syncwarp();

        float acc[8][4];
        #pragma unroll
        for (int r = 0; r < 8; r++)
            #pragma unroll
            for (int q = 0; q < 4; q++) acc[r][q] = 0.0f;

        for (int d4 = 0; d4 < 64; d4++) {
            float w[4][4];
            #pragma unroll
            for (int q = 0; q < 4; q++) {
                const float* wp = Wt + (lane + 32 * q) * WT_STRIDE + d4 * 4;
                w[q][0] = wp[0]; w[q][1] = wp[1]; w[q][2] = wp[2]; w[q][3] = wp[3];
            }
            #pragma unroll
            for (int r = 0; r < 8; r++) {
                float4 z = *(const float4*)(zb + r * 256 + d4 * 4);
                #pragma unroll
                for (int q = 0; q < 4; q++)
                    acc[r][q] += z.x * w[q][0] + z.y * w[q][1]
                               + z.z * w[q][2] + z.w * w[q][3];
            }
        }

        #pragma unroll
        for (int r = 0; r < 8; r++) {
            if (r >= nval) break;        // warp-uniform
            float best = -3.0e38f;
            int bc = 0;
            #pragma unroll
            for (int q = 0; q < 4; q++) {
                int ccol = lane + 32 * q;
                float s = acc[r][q] - hn_s[ccol];
                if (s > best) { best = s; bc = ccol; }
            }
            #pragma unroll
            for (int off = 1; off <= 16; off <<= 1) {
                float ov = __shfl_xor_sync(0xffffffffu, best, off);
                int   oc = __shfl_xor_sync(0xffffffffu, bc, off);
                if (ov > best || (ov == best && oc < bc)) { best = ov; bc = oc; }
            }
            if (lane == 0)
                atomicMax(&g_best[rows[r]], pack_key(best, col0 + bc));
        }
        __syncwarp();
    }
}

// ---------------------------------------------------------------------------
// 6) gather zq, commit-loss partials, scatter EMA sums/counts
// ---------------------------------------------------------------------------
__global__ void gather_scatter(const float* __restrict__ ze,
                               const float* __restrict__ W,
                               float* __restrict__ out)
{
    __shared__ float wsum[2];
    int row = blockIdx.x;
    int t   = threadIdx.x;            // 64 threads, float4 per thread
    if (row == 0 && t == 0) g_nsum = 0.0f;
    unsigned long long pk = g_best[row];
    int k = 0x0FFFFFFF - (int)(unsigned)(pk & 0xFFFFFFFFu);

    float4 z = ((const float4*)ze)[(size_t)row * 64 + t];
    float4 w = ((const float4*)W)[(size_t)k * 64 + t];

    ((float4*)(out + OFF_ZQ))[(size_t)row * 64 + t] = w;

    float dx = w.x - z.x, dy = w.y - z.y, dz = w.z - z.z, dw = w.w - z.w;
    float ss = dx*dx + dy*dy + dz*dz + dw*dw;

    int base = k * D_DIM + 4 * t;
    atomicAdd(&g_st[base + 0], z.x);
    atomicAdd(&g_st[base + 1], z.y);
    atomicAdd(&g_st[base + 2], z.z);
    atomicAdd(&g_st[base + 3], z.w);

    #pragma unroll
    for (int off = 16; off > 0; off >>= 1)
        ss += __shfl_down_sync(0xffffffffu, ss, off);
    if ((t & 31) == 0) wsum[t >> 5] = ss;
    __syncthreads();
    if (t == 0) {
        atomicAdd(&g_sse, wsum[0] + wsum[1]);
        atomicAdd(&g_nt[k], 1.0f);
        out[OFF_IDX + row] = (float)k;
    }
}

// ---------------------------------------------------------------------------
// 7) Nt_new + total count n + commit scalar
// ---------------------------------------------------------------------------
__global__ void finalizeN(const float* __restrict__ Nt, float* __restrict__ out) {
    int k = blockIdx.x * 256 + threadIdx.x;
    float v = GAMMA_F * Nt[k] + (1.0f - GAMMA_F) * g_nt[k];
    out[OFF_NT + k] = v;

    float s = v;
    #pragma unroll
    for (int off = 16; off > 0; off >>= 1)
        s += __shfl_down_sync(0xffffffffu, s, off);
    __shared__ float bs[8];
    if ((threadIdx.x & 31) == 0) bs[threadIdx.x >> 5] = s;
    __syncthreads();
    if (threadIdx.x == 0) {
        float b = 0.0f;
        #pragma unroll
        for (int w = 0; w < 8; w++) b += bs[w];
        atomicAdd(&g_nsum, b);
    }
    if (blockIdx.x == 0 && threadIdx.x == 0)
        out[OFF_COMMIT] = g_sse * (1.0f / (float)(N_ROWS * D_DIM));
}

// ---------------------------------------------------------------------------
// 8) mt_new, embedW_new = mt_new / Nn; read-then-zero the EMA scratch
// ---------------------------------------------------------------------------
__global__ void finalizeW(const float* __restrict__ mt,
                          const float* __restrict__ Nt,
                          float* __restrict__ out)
{
    int k = blockIdx.x;
    int d = threadIdx.x;
    float n   = g_nsum;
    float Ntn = GAMMA_F * Nt[k] + (1.0f - GAMMA_F) * g_nt[k];
    float inv = (n + (float)K_CODES * EPS_F) / ((Ntn + EPS_F) * n);
    int q = k * D_DIM + d;
    float m = GAMMA_F * mt[q] + (1.0f - GAMMA_F) * g_st[q];
    out[OFF_MT  + q] = m;
    out[OFF_EMB + q] = m * inv;
    g_st[q] = 0.0f;                       // re-zero for next graph replay
    __syncthreads();
    if (d == 0) g_nt[k] = 0.0f;
}

// ---------------------------------------------------------------------------
extern "C" void kernel_launch(void* const* d_in, const int* in_sizes, int n_in,
                              void* d_out, int out_size)
{
    const float* ze = (const float*)d_in[0];
    const float* W  = (const float*)d_in[1];
    const float* mt = (const float*)d_in[2];
    const float* Nt = (const float*)d_in[3];
    float* out = (float*)d_out;

    cudaFuncSetAttribute(gemm_p1,
                         cudaFuncAttributeMaxDynamicSharedMemorySize, SM_TOTAL);
    cudaFuncSetAttribute(rescore,
                         cudaFuncAttributeMaxDynamicSharedMemorySize, RS_SMEM);

    compute_hn    <<<K_CODES / 8, 256>>> (W);
    split_A       <<<N_ROWS * 64 / 256, 256>>> ((const float4*)ze);
    split_B       <<<K_CODES * 64 / 256, 256>>> ((const float4*)W);
    gemm_p1       <<<ROW_TILES * COL_TILES, 256, SM_TOTAL>>> ();
    rowreduce     <<<N_ROWS / 8, 256>>> ();
    rescore       <<<COL_TILES * 8, 256, RS_SMEM>>> (ze, W);
    gather_scatter<<<N_ROWS, 64>>> (ze, W, out);
    finalizeN     <<<K_CODES / 256, 256>>> (Nt, out);
    finalizeW     <<<K_CODES, 256>>> (mt, Nt, out);
}